// round 4
// baseline (speedup 1.0000x reference)
#include <cuda_runtime.h>
#include <cuda_bf16.h>
#include <cstdint>
#include <cstddef>

// ----- problem dims -----
#define MDIM 8192
#define NDIM 16384
#define KDIM 4096

// ----- tiling -----
#define BM 128
#define BN 128
#define KC 64
#define NUM_KITER (KDIM / KC)      // 64
#define TILES_M (MDIM / BM)        // 64
#define TILES_N (NDIM / BN)        // 128
#define NCTA (TILES_M * TILES_N)   // 8192
#define GROUP_M 16

// smem: 128 rows x 64B (KC int8), padded to 80B rows (conflict-free ldmatrix)
#define ROWB 80
#define ARR_BYTES (128 * ROWB)         // 10240
#define Q1_OFF 0
#define Q2_OFF ARR_BYTES
#define W_OFF  (2 * ARR_BYTES)
#define STAGE_BYTES (3 * ARR_BYTES)    // 30720
#define NSTAGE 4
#define SMEM_TOTAL (NSTAGE * STAGE_BYTES)  // 122880

// ----- device scratch -----
__device__ __align__(256) int8_t g_w8[(size_t)NDIM * KDIM];   // 64 MB
__device__ __align__(256) int8_t g_q1[(size_t)MDIM * KDIM];   // 32 MB
__device__ __align__(256) int8_t g_q2[(size_t)MDIM * KDIM];   // 32 MB
__device__ float g_s1[MDIM];

// ----- helpers -----
__device__ __forceinline__ uint32_t smem_u32(const void* p) {
    uint32_t a;
    asm("{ .reg .u64 t; cvta.to.shared.u64 t, %1; cvt.u32.u64 %0, t; }" : "=r"(a) : "l"(p));
    return a;
}
__device__ __forceinline__ void cp16(uint32_t dst, const void* src) {
    asm volatile("cp.async.cg.shared.global [%0], [%1], 16;"
                 :: "r"(dst), "l"(__cvta_generic_to_global(src)) : "memory");
}
__device__ __forceinline__ void ldsm4(uint32_t& r0, uint32_t& r1, uint32_t& r2, uint32_t& r3,
                                      uint32_t addr) {
    asm volatile("ldmatrix.sync.aligned.m8n8.x4.shared.b16 {%0,%1,%2,%3}, [%4];"
                 : "=r"(r0), "=r"(r1), "=r"(r2), "=r"(r3) : "r"(addr));
}
__device__ __forceinline__ void imma(int* c, const uint32_t* a, const uint32_t* b) {
    asm volatile(
        "mma.sync.aligned.m16n8k32.row.col.s32.s8.s8.s32 "
        "{%0,%1,%2,%3}, {%4,%5,%6,%7}, {%8,%9}, {%0,%1,%2,%3};"
        : "+r"(c[0]), "+r"(c[1]), "+r"(c[2]), "+r"(c[3])
        : "r"(a[0]), "r"(a[1]), "r"(a[2]), "r"(a[3]), "r"(b[0]), "r"(b[1]));
}
__device__ __forceinline__ int pack4(int b0, int b1, int b2, int b3) {
    return (b0 & 0xFF) | ((b1 & 0xFF) << 8) | ((b2 & 0xFF) << 16) | (b3 << 24);
}

// ----- W: int32 -> int8 (exact). thread handles 16 ints -> 16 bytes -----
__global__ void __launch_bounds__(256) k_wconv(const int4* __restrict__ wq) {
    size_t i = (size_t)blockIdx.x * 256 + threadIdx.x;
    int4 a = wq[i * 4 + 0], b = wq[i * 4 + 1], c = wq[i * 4 + 2], d = wq[i * 4 + 3];
    int4 o;
    o.x = pack4(a.x, a.y, a.z, a.w);
    o.y = pack4(b.x, b.y, b.z, b.w);
    o.z = pack4(c.x, c.y, c.z, c.w);
    o.w = pack4(d.x, d.y, d.z, d.w);
    ((int4*)g_w8)[i] = o;
}

// ----- x: two-level int8 quantization per row -----
// x = s1*q1 + s2*q2, s1 = rowmax/127, s2 = s1/254, |err| <= s1/508
__global__ void __launch_bounds__(256) k_xq(const float* __restrict__ x) {
    int row = blockIdx.x, t = threadIdx.x;
    const float4* xr = (const float4*)(x + (size_t)row * KDIM);
    float4 v[4];
    float amax = 0.f;
#pragma unroll
    for (int j = 0; j < 4; j++) {
        v[j] = xr[t + j * 256];
        amax = fmaxf(amax, fmaxf(fmaxf(fabsf(v[j].x), fabsf(v[j].y)),
                                 fmaxf(fabsf(v[j].z), fabsf(v[j].w))));
    }
#pragma unroll
    for (int o = 16; o; o >>= 1) amax = fmaxf(amax, __shfl_xor_sync(0xFFFFFFFFu, amax, o));
    __shared__ float wmax[8];
    if ((t & 31) == 0) wmax[t >> 5] = amax;
    __syncthreads();
    float m = wmax[0];
#pragma unroll
    for (int j = 1; j < 8; j++) m = fmaxf(m, wmax[j]);
    m = fmaxf(m, 1e-30f);
    float s1 = m * (1.f / 127.f);
    float inv1 = 127.f / m;
    float inv2 = inv1 * 254.f;
    if (t == 0) g_s1[row] = s1;

    int* q1o = (int*)(g_q1 + (size_t)row * KDIM);
    int* q2o = (int*)(g_q2 + (size_t)row * KDIM);
#pragma unroll
    for (int j = 0; j < 4; j++) {
        float xs[4] = {v[j].x, v[j].y, v[j].z, v[j].w};
        int q1b[4], q2b[4];
#pragma unroll
        for (int e = 0; e < 4; e++) {
            float q = rintf(xs[e] * inv1);
            float r = xs[e] - q * s1;
            q1b[e] = (int)q;
            q2b[e] = (int)rintf(r * inv2);
        }
        q1o[t + j * 256] = pack4(q1b[0], q1b[1], q1b[2], q1b[3]);
        q2o[t + j * 256] = pack4(q2b[0], q2b[1], q2b[2], q2b[3]);
    }
}

// ----- cp.async one K-chunk (KC=64 int8) into a stage -----
__device__ __forceinline__ void load_chunk(uint32_t stage, int tm, int tn, int kk, int tid) {
    int row = tid >> 1;
    int cb  = (tid & 1) * 32;   // byte offset within 64B row
    const int8_t* q1 = g_q1 + ((size_t)(tm * BM + row)) * KDIM + kk + cb;
    const int8_t* q2 = g_q2 + ((size_t)(tm * BM + row)) * KDIM + kk + cb;
    const int8_t* wb = g_w8 + ((size_t)(tn * BN + row)) * KDIM + kk + cb;
    uint32_t so = stage + (uint32_t)(row * ROWB + cb);
    cp16(so + Q1_OFF, q1);  cp16(so + Q1_OFF + 16, q1 + 16);
    cp16(so + Q2_OFF, q2);  cp16(so + Q2_OFF + 16, q2 + 16);
    cp16(so + W_OFF,  wb);  cp16(so + W_OFF  + 16, wb + 16);
}

// ----- main GEMM: 128x128 tile, IMMA s8 two-level, s32 accum -----
__global__ void __launch_bounds__(256, 1) k_gemm(const float* __restrict__ scale,
                                                 const float* __restrict__ bias,
                                                 float* __restrict__ out) {
    extern __shared__ char smem[];
    uint32_t sbase = smem_u32(smem);
    int tid = threadIdx.x, wid = tid >> 5, lane = tid & 31;

    int bid   = blockIdx.x;
    int group = bid / (GROUP_M * TILES_N);
    int rem   = bid % (GROUP_M * TILES_N);
    int tm    = group * GROUP_M + (rem % GROUP_M);
    int tn    = rem / GROUP_M;

    int wm = wid & 3;     // 32-row M sub-block
    int wn = wid >> 2;    // 64-col N sub-block

    int acc1[2][8][4], acc2[2][8][4];
#pragma unroll
    for (int i = 0; i < 2; i++)
#pragma unroll
        for (int j = 0; j < 8; j++)
#pragma unroll
            for (int k = 0; k < 4; k++) { acc1[i][j][k] = 0; acc2[i][j][k] = 0; }

    // prologue: fill 3 stages
    load_chunk(sbase + 0 * STAGE_BYTES, tm, tn, 0 * KC, tid);
    asm volatile("cp.async.commit_group;" ::: "memory");
    load_chunk(sbase + 1 * STAGE_BYTES, tm, tn, 1 * KC, tid);
    asm volatile("cp.async.commit_group;" ::: "memory");
    load_chunk(sbase + 2 * STAGE_BYTES, tm, tn, 2 * KC, tid);
    asm volatile("cp.async.commit_group;" ::: "memory");

    // ldmatrix per-lane address components
    int a_row = wm * 32 + (lane & 15);
    int a_cb  = (lane >> 4) * 16;
    int b_row = wn * 64 + ((lane >> 4) & 1) * 8 + (lane & 7);
    int b_cb  = ((lane >> 3) & 1) * 16;

    int stg = 0;
#pragma unroll 1
    for (int i = 0; i < NUM_KITER; i++) {
        asm volatile("cp.async.wait_group 2;" ::: "memory");
        __syncthreads();
        uint32_t cur = sbase + (uint32_t)stg * STAGE_BYTES;

        if (i + 3 < NUM_KITER) {
            int ns = stg + 3; if (ns >= NSTAGE) ns -= NSTAGE;
            load_chunk(sbase + (uint32_t)ns * STAGE_BYTES, tm, tn, (i + 3) * KC, tid);
        }
        asm volatile("cp.async.commit_group;" ::: "memory");

#pragma unroll
        for (int ks = 0; ks < 2; ks++) {
            uint32_t a1[2][4], a2[2][4], bf[8][2];
#pragma unroll
            for (int mf = 0; mf < 2; mf++) {
                uint32_t aaddr = cur + (uint32_t)((a_row + mf * 16) * ROWB + a_cb + ks * 32);
                ldsm4(a1[mf][0], a1[mf][1], a1[mf][2], a1[mf][3], aaddr + Q1_OFF);
                ldsm4(a2[mf][0], a2[mf][1], a2[mf][2], a2[mf][3], aaddr + Q2_OFF);
            }
#pragma unroll
            for (int nf2 = 0; nf2 < 4; nf2++) {
                uint32_t baddr = cur + W_OFF +
                    (uint32_t)((b_row + nf2 * 16) * ROWB + b_cb + ks * 32);
                ldsm4(bf[nf2 * 2][0], bf[nf2 * 2][1],
                      bf[nf2 * 2 + 1][0], bf[nf2 * 2 + 1][1], baddr);
            }
#pragma unroll
            for (int mf = 0; mf < 2; mf++)
#pragma unroll
                for (int nf = 0; nf < 8; nf++) {
                    imma(acc1[mf][nf], a1[mf], bf[nf]);
                    imma(acc2[mf][nf], a2[mf], bf[nf]);
                }
        }
        stg = stg + 1; if (stg >= NSTAGE) stg = 0;
    }

    // ----- epilogue: y = s1[m]*(a1 + a2/254)*scale[n] + bias[n] -----
    int n_base = tn * BN + wn * 64 + (lane & 3) * 2;
    float sc[8][2], bi[8][2];
#pragma unroll
    for (int nf = 0; nf < 8; nf++) {
        int n = n_base + nf * 8;
        sc[nf][0] = scale[n];     sc[nf][1] = scale[n + 1];
        bi[nf][0] = bias[n];      bi[nf][1] = bias[n + 1];
    }
    int m_base = tm * BM + wm * 32 + (lane >> 2);
    const float INV254 = 1.f / 254.f;
#pragma unroll
    for (int mf = 0; mf < 2; mf++) {
#pragma unroll
        for (int half = 0; half < 2; half++) {
            int mrow = m_base + mf * 16 + half * 8;
            float s1 = g_s1[mrow];
            float* orow = out + (size_t)mrow * NDIM + n_base;
#pragma unroll
            for (int nf = 0; nf < 8; nf++) {
                float c0 = (float)acc1[mf][nf][half * 2 + 0] +
                           (float)acc2[mf][nf][half * 2 + 0] * INV254;
                float c1 = (float)acc1[mf][nf][half * 2 + 1] +
                           (float)acc2[mf][nf][half * 2 + 1] * INV254;
                float2 v;
                v.x = fmaf(c0, s1 * sc[nf][0], bi[nf][0]);
                v.y = fmaf(c1, s1 * sc[nf][1], bi[nf][1]);
                *(float2*)(orow + nf * 8) = v;
            }
        }
    }
}

extern "C" void kernel_launch(void* const* d_in, const int* in_sizes, int n_in,
                              void* d_out, int out_size) {
    const float* x     = (const float*)d_in[0];
    const int*   wq    = (const int*)d_in[1];
    const float* scale = (const float*)d_in[2];
    const float* bias  = (const float*)d_in[3];
    float* out = (float*)d_out;

    k_wconv<<<(int)(((size_t)NDIM * KDIM) / (256 * 16)), 256>>>((const int4*)wq);
    k_xq<<<MDIM, 256>>>(x);

    cudaFuncSetAttribute(k_gemm, cudaFuncAttributeMaxDynamicSharedMemorySize, SMEM_TOTAL);
    k_gemm<<<NCTA, 256, SMEM_TOTAL>>>(scale, bias, out);
}

// round 5
// speedup vs baseline: 6.8451x; 6.8451x over previous
#include <cuda_runtime.h>
#include <cuda_fp16.h>
#include <cstdint>
#include <cstddef>

// ----- problem dims -----
#define MDIM 8192
#define NDIM 16384
#define KDIM 4096

// ----- tiling -----
#define BM 128
#define BN 256
#define KC 64
#define NUM_KITER (KDIM / KC)      // 64
#define TILES_M (MDIM / BM)        // 64
#define TILES_N (NDIM / BN)        // 64
#define NCTA (TILES_M * TILES_N)   // 4096
#define GROUP_M 16

// packed block sizes (bytes): smem-image layout, SW128 swizzled
#define A_BLK 16384                // 128 rows x 128B
#define B_BLK 32768                // 256 rows x 128B
#define STAGE_BYTES (A_BLK + B_BLK)   // 49152
#define NSTAGE 3
#define SMEM_DATA 1024
#define SMEM_TOTAL (SMEM_DATA + NSTAGE * STAGE_BYTES)   // 148480
#define A_OFF 0
#define B_OFF A_BLK

#define SWZ128(x) ((x) ^ (((x) >> 3) & 0x70))

// ----- device scratch: packed fp16 images -----
__device__ __align__(1024) __half g_xp[(size_t)MDIM * KDIM];   //  64 MB
__device__ __align__(1024) __half g_wp[(size_t)NDIM * KDIM];   // 128 MB

// ----- helpers -----
__device__ __forceinline__ uint32_t smem_u32(const void* p) {
    uint32_t a;
    asm("{ .reg .u64 t; cvta.to.shared.u64 t, %1; cvt.u32.u64 %0, t; }" : "=r"(a) : "l"(p));
    return a;
}
__device__ __forceinline__ void mbar_init(uint32_t a, uint32_t cnt) {
    asm volatile("mbarrier.init.shared.b64 [%0], %1;" :: "r"(a), "r"(cnt) : "memory");
}
__device__ __forceinline__ void mbar_expect_tx(uint32_t a, uint32_t bytes) {
    asm volatile("mbarrier.arrive.expect_tx.shared.b64 _, [%0], %1;"
                 :: "r"(a), "r"(bytes) : "memory");
}
__device__ __forceinline__ void mbar_wait(uint32_t a, uint32_t parity) {
    uint32_t done;
    asm volatile(
        "{ .reg .pred p; mbarrier.try_wait.parity.acquire.cta.shared::cta.b64 p, [%1], %2; selp.b32 %0,1,0,p; }"
        : "=r"(done) : "r"(a), "r"(parity) : "memory");
    if (!done) {
        asm volatile(
            "{ .reg .pred P;\n"
            "WL_%=:\n"
            "mbarrier.try_wait.parity.acquire.cta.shared::cta.b64 P, [%0], %1, 0x989680;\n"
            "@P bra WD_%=;\n"
            "bra WL_%=;\n"
            "WD_%=: }"
            :: "r"(a), "r"(parity) : "memory");
    }
}
__device__ __forceinline__ void bulk_cp(uint32_t dst, const void* src, uint32_t bytes,
                                        uint32_t mbar) {
    asm volatile(
        "cp.async.bulk.shared::cluster.global.mbarrier::complete_tx::bytes [%0], [%1], %2, [%3];"
        :: "r"(dst), "l"(__cvta_generic_to_global(src)), "r"(bytes), "r"(mbar) : "memory");
}
__device__ __forceinline__ void ldsm4(uint32_t& r0, uint32_t& r1, uint32_t& r2, uint32_t& r3,
                                      uint32_t addr) {
    asm volatile("ldmatrix.sync.aligned.m8n8.x4.shared.b16 {%0,%1,%2,%3}, [%4];"
                 : "=r"(r0), "=r"(r1), "=r"(r2), "=r"(r3) : "r"(addr));
}
__device__ __forceinline__ void mma16816(float* c, const uint32_t* a, const uint32_t* b) {
    asm volatile(
        "mma.sync.aligned.m16n8k16.row.col.f32.f16.f16.f32 "
        "{%0,%1,%2,%3}, {%4,%5,%6,%7}, {%8,%9}, {%0,%1,%2,%3};"
        : "+f"(c[0]), "+f"(c[1]), "+f"(c[2]), "+f"(c[3])
        : "r"(a[0]), "r"(a[1]), "r"(a[2]), "r"(a[3]), "r"(b[0]), "r"(b[1]));
}

// ----- W: int32 -> packed fp16 smem-image (exact) -----
// thread t handles one 16B chunk: row o = t>>9, chunk-in-row k8 = t&511
__global__ void __launch_bounds__(256) k_wconv(const int4* __restrict__ wq) {
    size_t t = (size_t)blockIdx.x * 256 + threadIdx.x;
    int o  = (int)(t >> 9);
    int k8 = (int)(t & 511);
    int4 a = wq[t * 2], b = wq[t * 2 + 1];
    __half2 h[4];
    h[0] = __floats2half2_rn((float)a.x, (float)a.y);
    h[1] = __floats2half2_rn((float)a.z, (float)a.w);
    h[2] = __floats2half2_rn((float)b.x, (float)b.y);
    h[3] = __floats2half2_rn((float)b.z, (float)b.w);
    int tile = o >> 8, kk = k8 >> 3, c = k8 & 7;
    size_t base = ((size_t)(tile * NUM_KITER + kk)) * B_BLK;
    uint32_t off = SWZ128((uint32_t)(((o & 255) << 7) + (c << 4)));
    *(uint4*)((char*)g_wp + base + off) = *(uint4*)h;
}

// ----- x: fp32 -> packed fp16 smem-image -----
__global__ void __launch_bounds__(256) k_xconv(const float4* __restrict__ x) {
    size_t t = (size_t)blockIdx.x * 256 + threadIdx.x;
    int m  = (int)(t >> 9);
    int k8 = (int)(t & 511);
    float4 a = x[t * 2], b = x[t * 2 + 1];
    __half2 h[4];
    h[0] = __floats2half2_rn(a.x, a.y);
    h[1] = __floats2half2_rn(a.z, a.w);
    h[2] = __floats2half2_rn(b.x, b.y);
    h[3] = __floats2half2_rn(b.z, b.w);
    int tile = m >> 7, kk = k8 >> 3, c = k8 & 7;
    size_t base = ((size_t)(tile * NUM_KITER + kk)) * A_BLK;
    uint32_t off = SWZ128((uint32_t)(((m & 127) << 7) + (c << 4)));
    *(uint4*)((char*)g_xp + base + off) = *(uint4*)h;
}

// ----- main GEMM: 128x256 tile, fp16 HMMA, bulk-copy pipeline -----
__global__ void __launch_bounds__(512, 1) k_gemm(const float* __restrict__ scale,
                                                 const float* __restrict__ bias,
                                                 float* __restrict__ out) {
    extern __shared__ char smem[];
    uint32_t sbase = smem_u32(smem);
    int tid = threadIdx.x, wid = tid >> 5, lane = tid & 31;

    // grouped rasterization for L2 reuse
    int bid   = blockIdx.x;
    int group = bid / (GROUP_M * TILES_N);
    int rem   = bid % (GROUP_M * TILES_N);
    int tm    = group * GROUP_M + (rem % GROUP_M);
    int tn    = rem / GROUP_M;

    int wm = wid & 3;     // 32-row M sub-block
    int wn = wid >> 2;    // 64-col N sub-block

    const char* asrc = (const char*)g_xp + (size_t)tm * NUM_KITER * A_BLK;
    const char* bsrc = (const char*)g_wp + (size_t)tn * NUM_KITER * B_BLK;

    if (tid == 0) {
        mbar_init(sbase + 0, 1);
        mbar_init(sbase + 8, 1);
        mbar_init(sbase + 16, 1);
    }
    __syncthreads();

    // prologue: fill 3 stages
    if (tid == 0) {
#pragma unroll
        for (int j = 0; j < NSTAGE; j++) {
            uint32_t mb = sbase + j * 8;
            uint32_t st = sbase + SMEM_DATA + j * STAGE_BYTES;
            mbar_expect_tx(mb, STAGE_BYTES);
            bulk_cp(st + A_OFF, asrc + (size_t)j * A_BLK, A_BLK, mb);
            bulk_cp(st + B_OFF, bsrc + (size_t)j * B_BLK, B_BLK, mb);
        }
    }

    float acc[2][8][4];
#pragma unroll
    for (int i = 0; i < 2; i++)
#pragma unroll
        for (int j = 0; j < 8; j++)
#pragma unroll
            for (int k = 0; k < 4; k++) acc[i][j][k] = 0.f;

    // ldmatrix per-lane components (offsets within swizzled 128B-row image)
    int a_row = wm * 32 + (lane & 15);
    int a_cb  = (lane >> 4) * 16;
    int b_row = wn * 64 + ((lane >> 4) & 1) * 8 + (lane & 7);
    int b_cb  = ((lane >> 3) & 1) * 16;

    int stg = 0;
#pragma unroll 1
    for (int i = 0; i < NUM_KITER; i++) {
        uint32_t cur = sbase + SMEM_DATA + (uint32_t)stg * STAGE_BYTES;
        mbar_wait(sbase + stg * 8, (uint32_t)((i / NSTAGE) & 1));

#pragma unroll
        for (int ks = 0; ks < 4; ks++) {
            uint32_t af[2][4], bf[8][2];
#pragma unroll
            for (int mf = 0; mf < 2; mf++) {
                uint32_t off = (uint32_t)((a_row + mf * 16) * 128 + a_cb + ks * 32);
                ldsm4(af[mf][0], af[mf][1], af[mf][2], af[mf][3],
                      cur + A_OFF + SWZ128(off));
            }
#pragma unroll
            for (int nf2 = 0; nf2 < 4; nf2++) {
                uint32_t off = (uint32_t)((b_row + nf2 * 16) * 128 + b_cb + ks * 32);
                ldsm4(bf[nf2 * 2][0], bf[nf2 * 2][1],
                      bf[nf2 * 2 + 1][0], bf[nf2 * 2 + 1][1],
                      cur + B_OFF + SWZ128(off));
            }
#pragma unroll
            for (int mf = 0; mf < 2; mf++)
#pragma unroll
                for (int nf = 0; nf < 8; nf++)
                    mma16816(acc[mf][nf], af[mf], bf[nf]);
        }
        __syncthreads();
        if (tid == 0 && i + NSTAGE < NUM_KITER) {
            uint32_t mb = sbase + stg * 8;
            mbar_expect_tx(mb, STAGE_BYTES);
            bulk_cp(cur + A_OFF, asrc + (size_t)(i + NSTAGE) * A_BLK, A_BLK, mb);
            bulk_cp(cur + B_OFF, bsrc + (size_t)(i + NSTAGE) * B_BLK, B_BLK, mb);
        }
        stg = stg + 1; if (stg >= NSTAGE) stg = 0;
    }

    // ----- epilogue: y = acc * scale[n] + bias[n] -----
    int n_base = tn * BN + wn * 64 + (lane & 3) * 2;
    float sc[8][2], bi[8][2];
#pragma unroll
    for (int nf = 0; nf < 8; nf++) {
        int n = n_base + nf * 8;
        sc[nf][0] = scale[n];     sc[nf][1] = scale[n + 1];
        bi[nf][0] = bias[n];      bi[nf][1] = bias[n + 1];
    }
    int m_base = tm * BM + wm * 32 + (lane >> 2);
#pragma unroll
    for (int mf = 0; mf < 2; mf++) {
#pragma unroll
        for (int half = 0; half < 2; half++) {
            size_t row = (size_t)(m_base + mf * 16 + half * 8);
            float* orow = out + row * NDIM + n_base;
#pragma unroll
            for (int nf = 0; nf < 8; nf++) {
                float2 v;
                v.x = fmaf(acc[mf][nf][half * 2 + 0], sc[nf][0], bi[nf][0]);
                v.y = fmaf(acc[mf][nf][half * 2 + 1], sc[nf][1], bi[nf][1]);
                *(float2*)(orow + nf * 8) = v;
            }
        }
    }
}

extern "C" void kernel_launch(void* const* d_in, const int* in_sizes, int n_in,
                              void* d_out, int out_size) {
    const float* x     = (const float*)d_in[0];
    const int*   wq    = (const int*)d_in[1];
    const float* scale = (const float*)d_in[2];
    const float* bias  = (const float*)d_in[3];
    float* out = (float*)d_out;

    k_wconv<<<(int)(((size_t)NDIM * KDIM) / (256 * 8)), 256>>>((const int4*)wq);   // 32768
    k_xconv<<<(int)(((size_t)MDIM * KDIM) / (256 * 8)), 256>>>((const float4*)x);  // 16384

    cudaFuncSetAttribute(k_gemm, cudaFuncAttributeMaxDynamicSharedMemorySize, SMEM_TOTAL);
    k_gemm<<<NCTA, 512, SMEM_TOTAL>>>(scale, bias, out);
}